// round 16
// baseline (speedup 1.0000x reference)
#include <cuda_runtime.h>
#include <cuda_fp16.h>
#include <cstdint>

// Problem constants (fixed by reference_code)
#define NMAX 50000
#define EMAX 800000
#define F    256
#define AK   512          // concat K for layer-1 GEMM (agg | x)
#define NCLS 40
#define N2   80           // combined layer-2 output width [w2_l | w2_r]
#define SCAN_TILE 1024
#define NBLK_MAX  64

// ---------------- scratch (static device globals; no runtime allocation) ----
__device__ int   g_is64;
__device__ int   g_deg[NMAX];
__device__ int   g_rowptr[NMAX + 1];
__device__ int   g_col[EMAX];
__device__ int   g_pos[EMAX];            // per-edge slot within dst bucket
__device__ unsigned long long g_scan_state[NBLK_MAX];  // (flag<<62)|value
__device__ int   g_scan_ticket;
__device__ float g_invdeg[NMAX];
__device__ __align__(16) __half g_Ah[(size_t)NMAX * AK];   // [agg | x] fp16
__device__ __align__(16) __half g_Bh[(size_t)F * AK];      // [w1_l | w1_r] fp16
__device__ __align__(16) __half g_Hh[(size_t)NMAX * F];    // relu(h) fp16
__device__ __align__(16) __half g_B2h[(size_t)N2 * F];     // [w2_l | w2_r] fp16
__device__ __align__(16) __half g_t[(size_t)NMAX * NCLS];  // h @ w2_l^T (fp16)
__device__ __align__(16) float g_u[(size_t)NMAX * NCLS];   // h @ w2_r^T (fp32)

// ---------------- PTX helpers ----------------------------------------------
__device__ __forceinline__ void ldsm_x4(uint32_t& r0, uint32_t& r1,
                                        uint32_t& r2, uint32_t& r3, uint32_t addr) {
    asm volatile("ldmatrix.sync.aligned.m8n8.x4.shared.b16 {%0,%1,%2,%3},[%4];"
                 : "=r"(r0), "=r"(r1), "=r"(r2), "=r"(r3) : "r"(addr));
}
__device__ __forceinline__ void ldsm_x2(uint32_t& r0, uint32_t& r1, uint32_t addr) {
    asm volatile("ldmatrix.sync.aligned.m8n8.x2.shared.b16 {%0,%1},[%2];"
                 : "=r"(r0), "=r"(r1) : "r"(addr));
}
__device__ __forceinline__ void mma_f16(float* c, const uint32_t* a, const uint32_t* b) {
    asm volatile("mma.sync.aligned.m16n8k16.row.col.f32.f16.f16.f32 "
                 "{%0,%1,%2,%3},{%4,%5,%6,%7},{%8,%9},{%0,%1,%2,%3};"
                 : "+f"(c[0]), "+f"(c[1]), "+f"(c[2]), "+f"(c[3])
                 : "r"(a[0]), "r"(a[1]), "r"(a[2]), "r"(a[3]), "r"(b[0]), "r"(b[1]));
}
__device__ __forceinline__ void cp16(uint32_t saddr, const void* gaddr, int sz) {
    asm volatile("cp.async.cg.shared.global [%0],[%1],16,%2;"
                 :: "r"(saddr), "l"(gaddr), "r"(sz));
}
__device__ __forceinline__ void cp_commit() {
    asm volatile("cp.async.commit_group;");
}
template <int N>
__device__ __forceinline__ void cp_wait() {
    asm volatile("cp.async.wait_group %0;" :: "n"(N));
}
__device__ __forceinline__ void cp_wait_all() {
    asm volatile("cp.async.commit_group;");
    asm volatile("cp.async.wait_group 0;");
}

__device__ __forceinline__ int edge_at(const void* edges, size_t idx) {
    if (g_is64) return (int)((const long long*)edges)[idx];
    return ((const int*)edges)[idx];
}

// load 4 consecutive edge entries starting at idx (idx 4-aligned, idx+3 < limit)
__device__ __forceinline__ void edge4(const void* edges, size_t idx, int* v) {
    if (g_is64) {
        const longlong2* p = (const longlong2*)((const long long*)edges + idx);
        longlong2 a = p[0], b = p[1];
        v[0] = (int)a.x; v[1] = (int)a.y; v[2] = (int)b.x; v[3] = (int)b.y;
    } else {
        int4 a = *(const int4*)((const int*)edges + idx);
        v[0] = a.x; v[1] = a.y; v[2] = a.z; v[3] = a.w;
    }
}

// ---------------- init: zero counters + scan state + dtype probe ------------
__global__ void init_kernel(const int* __restrict__ v, int n) {
    int i = blockIdx.x * blockDim.x + threadIdx.x;
    if (i < n) g_deg[i] = 0;
    if (blockIdx.x == 0) {
        if (threadIdx.x < NBLK_MAX) g_scan_state[threadIdx.x] = 0ULL;
        __shared__ int any_nonzero;
        if (threadIdx.x == 0) { any_nonzero = 0; g_scan_ticket = 0; }
        __syncthreads();
        if (v[2 * threadIdx.x + 1] != 0) atomicOr(&any_nonzero, 1);
        __syncthreads();
        if (threadIdx.x == 0) g_is64 = (any_nonzero == 0) ? 1 : 0;
    }
}

// ---------------- CSR build ------------------------------------------------
// degree pass, 4 edges per thread (MLP=4): records per-edge slot in g_pos
__global__ void degree_kernel(const void* __restrict__ edges, int E) {
    int base = (blockIdx.x * blockDim.x + threadIdx.x) * 4;
    if (base + 4 <= E) {
        int d[4];
        edge4(edges, (size_t)E + base, d);
#pragma unroll
        for (int j = 0; j < 4; j++)
            g_pos[base + j] = atomicAdd(&g_deg[d[j]], 1);
    } else {
        for (int e = base; e < E; e++) {
            int d = edge_at(edges, (size_t)E + e);
            g_pos[e] = atomicAdd(&g_deg[d], 1);
        }
    }
}
__device__ __forceinline__ int block_incl_scan(int d, int* total) {
    __shared__ int wsum[32];
    int lane = threadIdx.x & 31, wid = threadIdx.x >> 5;
    int v = d;
#pragma unroll
    for (int o = 1; o < 32; o <<= 1) {
        int t = __shfl_up_sync(0xffffffffu, v, o);
        if (lane >= o) v += t;
    }
    if (lane == 31) wsum[wid] = v;
    __syncthreads();
    if (wid == 0) {
        int w = wsum[lane];
#pragma unroll
        for (int o = 1; o < 32; o <<= 1) {
            int t = __shfl_up_sync(0xffffffffu, w, o);
            if (lane >= o) w += t;
        }
        wsum[lane] = w;
    }
    __syncthreads();
    int incl = v + (wid > 0 ? wsum[wid - 1] : 0);
    *total = wsum[31];
    __syncthreads();
    return incl;
}

// single-pass decoupled-lookback scan: g_deg -> g_rowptr (+invdeg, rowptr[n])
__global__ void scan_lookback_kernel(int n, int E) {
    __shared__ int s_bid;
    __shared__ int s_prefix;
    if (threadIdx.x == 0) s_bid = atomicAdd(&g_scan_ticket, 1);
    __syncthreads();
    int bid = s_bid;
    int i = bid * SCAN_TILE + threadIdx.x;
    int d = (i < n) ? g_deg[i] : 0;
    int total;
    int incl = block_incl_scan(d, &total);
    if (threadIdx.x == 0) {
        if (bid == 0) {
            atomicExch(&g_scan_state[0], (2ULL << 62) | (unsigned)total);
            s_prefix = 0;
        } else {
            atomicExch(&g_scan_state[bid], (1ULL << 62) | (unsigned)total);
            int prefix = 0;
            int j = bid - 1;
            while (j >= 0) {
                unsigned long long st = atomicAdd(&g_scan_state[j], 0ULL);
                unsigned long long flag = st >> 62;
                if (flag == 2) { prefix += (int)(st & 0xFFFFFFFFu); break; }
                if (flag == 1) { prefix += (int)(st & 0xFFFFFFFFu); j--; }
            }
            atomicExch(&g_scan_state[bid], (2ULL << 62) | (unsigned)(prefix + total));
            s_prefix = prefix;
        }
    }
    __syncthreads();
    if (i < n) {
        g_rowptr[i] = s_prefix + incl - d;
        g_invdeg[i] = 1.0f / (float)(d > 0 ? d : 1);
        if (i == n - 1) g_rowptr[n] = E;
    }
}

// scatter without atomics, 4 edges per thread (MLP=4)
__global__ void scatter_kernel(const void* __restrict__ edges, int E) {
    int base = (blockIdx.x * blockDim.x + threadIdx.x) * 4;
    if (base + 4 <= E) {
        int s[4], d[4];
        edge4(edges, (size_t)base, s);
        edge4(edges, (size_t)E + base, d);
        int4 p = *(const int4*)&g_pos[base];
        int rp[4];
        rp[0] = g_rowptr[d[0]]; rp[1] = g_rowptr[d[1]];
        rp[2] = g_rowptr[d[2]]; rp[3] = g_rowptr[d[3]];
        g_col[rp[0] + p.x] = s[0];
        g_col[rp[1] + p.y] = s[1];
        g_col[rp[2] + p.z] = s[2];
        g_col[rp[3] + p.w] = s[3];
    } else {
        for (int e = base; e < E; e++) {
            int srcv = edge_at(edges, e);
            int d    = edge_at(edges, (size_t)E + e);
            g_col[g_rowptr[d] + g_pos[e]] = srcv;
        }
    }
}

// ---------------- merged weight conversions (fp16) ---------------------------
#define W1_Q (F * (F / 4))          // 16384 float4s
#define W2_Q (N2 * (F / 4))         // 5120 float4s
__device__ __forceinline__ uint2 to_h4(float4 v) {
    __half2 h0 = __floats2half2_rn(v.x, v.y);
    __half2 h1 = __floats2half2_rn(v.z, v.w);
    return make_uint2(*(const uint32_t*)&h0, *(const uint32_t*)&h1);
}
__global__ void convert_weights_kernel(const float* __restrict__ w1_l,
                                       const float* __restrict__ w1_r,
                                       const float* __restrict__ w2_l,
                                       const float* __restrict__ w2_r) {
    int idx = blockIdx.x * blockDim.x + threadIdx.x;
    if (idx < W1_Q) {
        int row = idx / (F / 4), c4 = idx % (F / 4);
        float4 vl = *(const float4*)&w1_l[(size_t)row * F + c4 * 4];
        float4 vr = *(const float4*)&w1_r[(size_t)row * F + c4 * 4];
        size_t o = (size_t)row * AK + c4 * 4;
        *(uint2*)&g_Bh[o]     = to_h4(vl);
        *(uint2*)&g_Bh[o + F] = to_h4(vr);
    } else if (idx < W1_Q + W2_Q) {
        int j = idx - W1_Q;
        int row = j / (F / 4), c4 = j % (F / 4);
        const float* src = (row < NCLS) ? &w2_l[(size_t)row * F + c4 * 4]
                                        : &w2_r[(size_t)(row - NCLS) * F + c4 * 4];
        *(uint2*)&g_B2h[(size_t)row * F + c4 * 4] = to_h4(*(const float4*)src);
    }
}

// ---------------- x conversion: fp16 into A cols [256,512) ------------------
__global__ void convert_x_kernel(const float* __restrict__ x, int n) {
    int idx = blockIdx.x * blockDim.x + threadIdx.x;
    if (idx >= n * (F / 4)) return;
    int row = idx / (F / 4), c4 = idx % (F / 4);
    float4 v = *(const float4*)&x[(size_t)row * F + c4 * 4];
    *(uint2*)&g_Ah[(size_t)row * AK + F + c4 * 4] = to_h4(v);
}

// ---------------- mean aggregation (256-dim) from fp16 x-part ---------------
__global__ void aggregate_kernel(int n) {
    int node = blockIdx.x * blockDim.y + threadIdx.y;
    if (node >= n) return;
    int lane = threadIdx.x;
    int beg = g_rowptr[node], end = g_rowptr[node + 1];
    const uint4* xh = (const uint4*)g_Ah;   // row stride = 64 uint4; x-part +32
    float acc[8];
#pragma unroll
    for (int i = 0; i < 8; i++) acc[i] = 0.f;
    int e = beg;
    for (; e + 2 <= end; e += 2) {
        uint4 p0 = xh[(size_t)g_col[e] * 64 + 32 + lane];
        uint4 p1 = xh[(size_t)g_col[e + 1] * 64 + 32 + lane];
        const __half2* q0 = (const __half2*)&p0;
        const __half2* q1 = (const __half2*)&p1;
#pragma unroll
        for (int j = 0; j < 4; j++) {
            float2 f0 = __half22float2(q0[j]);
            float2 f1 = __half22float2(q1[j]);
            acc[j * 2]     += f0.x + f1.x;
            acc[j * 2 + 1] += f0.y + f1.y;
        }
    }
    if (e < end) {
        uint4 p0 = xh[(size_t)g_col[e] * 64 + 32 + lane];
        const __half2* q0 = (const __half2*)&p0;
#pragma unroll
        for (int j = 0; j < 4; j++) {
            float2 f0 = __half22float2(q0[j]);
            acc[j * 2]     += f0.x;
            acc[j * 2 + 1] += f0.y;
        }
    }
    float s = g_invdeg[node];
    uint4 o;
    __half2 h0 = __floats2half2_rn(acc[0] * s, acc[1] * s);
    __half2 h1 = __floats2half2_rn(acc[2] * s, acc[3] * s);
    __half2 h2 = __floats2half2_rn(acc[4] * s, acc[5] * s);
    __half2 h3 = __floats2half2_rn(acc[6] * s, acc[7] * s);
    o.x = *(const uint32_t*)&h0; o.y = *(const uint32_t*)&h1;
    o.z = *(const uint32_t*)&h2; o.w = *(const uint32_t*)&h3;
    *(uint4*)&g_Ah[(size_t)node * AK + lane * 8] = o;
}

// ---------------- GEMM1 (fp16 tensor cores, single pass, 2-stage pipeline) --
#define TSTRIDE 40      // halfs per smem row (80B) -> conflict-free ldsm
#define TILE_B  (128 * TSTRIDE * 2)   // bytes per tile = 10240
#define STAGE_B (2 * TILE_B)          // A + B tiles = 20480
extern __shared__ __align__(16) __half g1_smem[];
__global__ __launch_bounds__(256) void gemm1_tc_kernel(const float* __restrict__ bias0,
                                                       const float* __restrict__ bias1,
                                                       int M) {
    const uint32_t sb0 = (uint32_t)__cvta_generic_to_shared(g1_smem);
    int bm = blockIdx.x * 128, bn = blockIdx.y * 128;
    int tid = threadIdx.x, wid = tid >> 5, lane = tid & 31;
    int wm = (wid >> 2) * 64, wn = (wid & 3) * 32;

    float acc[4][4][4];
#pragma unroll
    for (int mf = 0; mf < 4; mf++)
#pragma unroll
        for (int nf = 0; nf < 4; nf++)
#pragma unroll
            for (int r = 0; r < 4; r++) acc[mf][nf][r] = 0.f;

    auto load_chunk = [&](int kc, int stage) {
        int k0 = kc * 32;
        uint32_t sbase = sb0 + stage * STAGE_B;
#pragma unroll
        for (int i = 0; i < 4; i++) {
            int idx = tid + i * 256;
            int t   = idx >> 9;          // 0 = A, 1 = B
            int rem = idx & 511;
            int row = rem >> 2, ch = rem & 3;
            uint32_t sa = sbase + t * TILE_B + row * 80 + ch * 16;
            if (t == 0) {
                int grow = bm + row;
                int gr = grow < M ? grow : (M - 1);
                cp16(sa, g_Ah + (size_t)gr * AK + k0 + ch * 8, grow < M ? 16 : 0);
            } else {
                cp16(sa, g_Bh + (size_t)(bn + row) * AK + k0 + ch * 8, 16);
            }
        }
        cp_commit();
    };

    load_chunk(0, 0);
#pragma unroll 1
    for (int kc = 0; kc < 16; kc++) {
        int stage = kc & 1;
        if (kc + 1 < 16) {
            load_chunk(kc + 1, stage ^ 1);
            cp_wait<1>();
        } else {
            cp_wait<0>();
        }
        __syncthreads();
        uint32_t sb = sb0 + stage * STAGE_B;
#pragma unroll
        for (int ks = 0; ks < 32; ks += 16) {
            uint32_t a[4][4], b[4][2];
            int akb = (ks + ((lane >> 4) << 3)) * 2;
#pragma unroll
            for (int mf = 0; mf < 4; mf++) {
                int row = wm + mf * 16 + (lane & 15);
                ldsm_x4(a[mf][0], a[mf][1], a[mf][2], a[mf][3],
                        sb + row * 80 + akb);
            }
            int brow0 = wn + ((lane >> 4) << 3) + (lane & 7);
            int bkb = (ks + (((lane >> 3) & 1) << 3)) * 2;
#pragma unroll
            for (int nf2 = 0; nf2 < 2; nf2++) {
                int row = brow0 + nf2 * 16;
                uint32_t r0, r1, r2, r3;
                ldsm_x4(r0, r1, r2, r3, sb + TILE_B + row * 80 + bkb);
                b[nf2 * 2][0] = r0; b[nf2 * 2][1] = r1;
                b[nf2 * 2 + 1][0] = r2; b[nf2 * 2 + 1][1] = r3;
            }
#pragma unroll
            for (int mf = 0; mf < 4; mf++)
#pragma unroll
                for (int nf = 0; nf < 4; nf++)
                    mma_f16(acc[mf][nf], a[mf], b[nf]);
        }
        __syncthreads();
    }
#pragma unroll
    for (int nf = 0; nf < 4; nf++) {
        int c = bn + wn + nf * 8 + 2 * (lane & 3);
        float bb0 = bias0[c] + bias1[c];
        float bb1 = bias0[c + 1] + bias1[c + 1];
#pragma unroll
        for (int mf = 0; mf < 4; mf++) {
            int r0 = bm + wm + mf * 16 + (lane >> 2);
            int r1 = r0 + 8;
            if (r0 < M) {
                *(__half2*)&g_Hh[(size_t)r0 * F + c] =
                    __floats2half2_rn(fmaxf(acc[mf][nf][0] + bb0, 0.f),
                                      fmaxf(acc[mf][nf][1] + bb1, 0.f));
            }
            if (r1 < M) {
                *(__half2*)&g_Hh[(size_t)r1 * F + c] =
                    __floats2half2_rn(fmaxf(acc[mf][nf][2] + bb0, 0.f),
                                      fmaxf(acc[mf][nf][3] + bb1, 0.f));
            }
        }
    }
}

// ---------------- GEMM40 (fp16 TC): g_t (fp16) | g_u (fp32) = h @ B2^T ------
#define A2_B (128 * 80)
#define B2_B (80 * 80)
__global__ __launch_bounds__(256) void gemm40_tc_kernel(int M) {
    __shared__ __align__(16) __half smem[(A2_B + B2_B) / 2];
    const uint32_t sb = (uint32_t)__cvta_generic_to_shared(smem);
    int bm = blockIdx.x * 128;
    int tid = threadIdx.x, wid = tid >> 5, lane = tid & 31;
    int wm = (wid & 3) * 32, wn = (wid >> 2) * 40;

    float acc[2][5][4];
#pragma unroll
    for (int mf = 0; mf < 2; mf++)
#pragma unroll
        for (int nf = 0; nf < 5; nf++)
#pragma unroll
            for (int r = 0; r < 4; r++) acc[mf][nf][r] = 0.f;

#pragma unroll 1
    for (int kc = 0; kc < 8; kc++) {
        int k0 = kc * 32;
        for (int idx = tid; idx < 832; idx += 256) {
            if (idx < 512) {
                int row = idx >> 2, ch = idx & 3;
                int grow = bm + row;
                int gr = grow < M ? grow : (M - 1);
                cp16(sb + row * 80 + ch * 16,
                     g_Hh + (size_t)gr * F + k0 + ch * 8, grow < M ? 16 : 0);
            } else {
                int j = idx - 512;
                int row = j >> 2, ch = j & 3;
                cp16(sb + A2_B + row * 80 + ch * 16,
                     g_B2h + (size_t)row * F + k0 + ch * 8, 16);
            }
        }
        cp_wait_all();
        __syncthreads();
#pragma unroll
        for (int ks = 0; ks < 32; ks += 16) {
            uint32_t a[2][4], b[5][2];
            int akb = (ks + ((lane >> 4) << 3)) * 2;
#pragma unroll
            for (int mf = 0; mf < 2; mf++) {
                int row = wm + mf * 16 + (lane & 15);
                ldsm_x4(a[mf][0], a[mf][1], a[mf][2], a[mf][3],
                        sb + row * 80 + akb);
            }
            int bkb = (ks + (((lane >> 3) & 1) << 3)) * 2;
            int brow0 = wn + ((lane >> 4) << 3) + (lane & 7);
#pragma unroll
            for (int nf2 = 0; nf2 < 2; nf2++) {
                int row = brow0 + nf2 * 16;
                uint32_t r0, r1, r2, r3;
                ldsm_x4(r0, r1, r2, r3, sb + A2_B + row * 80 + bkb);
                b[nf2 * 2][0] = r0; b[nf2 * 2][1] = r1;
                b[nf2 * 2 + 1][0] = r2; b[nf2 * 2 + 1][1] = r3;
            }
            {
                int row = wn + 32 + (lane & 7);
                ldsm_x2(b[4][0], b[4][1], sb + A2_B + row * 80 + bkb);
            }
#pragma unroll
            for (int mf = 0; mf < 2; mf++)
#pragma unroll
                for (int nf = 0; nf < 5; nf++)
                    mma_f16(acc[mf][nf], a[mf], b[nf]);
        }
        __syncthreads();
    }
    bool is_u = (wid >> 2) != 0;
#pragma unroll
    for (int nf = 0; nf < 5; nf++) {
        int c = (wn % 40) + nf * 8 + 2 * (lane & 3);
#pragma unroll
        for (int mf = 0; mf < 2; mf++) {
            int r0 = bm + wm + mf * 16 + (lane >> 2);
            int r1 = r0 + 8;
            if (is_u) {
                if (r0 < M) {
                    g_u[(size_t)r0 * NCLS + c]     = acc[mf][nf][0];
                    g_u[(size_t)r0 * NCLS + c + 1] = acc[mf][nf][1];
                }
                if (r1 < M) {
                    g_u[(size_t)r1 * NCLS + c]     = acc[mf][nf][2];
                    g_u[(size_t)r1 * NCLS + c + 1] = acc[mf][nf][3];
                }
            } else {
                if (r0 < M)
                    *(__half2*)&g_t[(size_t)r0 * NCLS + c] =
                        __floats2half2_rn(acc[mf][nf][0], acc[mf][nf][1]);
                if (r1 < M)
                    *(__half2*)&g_t[(size_t)r1 * NCLS + c] =
                        __floats2half2_rn(acc[mf][nf][2], acc[mf][nf][3]);
            }
        }
    }
}

// ---------------- mean aggregation (40-dim, fp16 t) + fused final -----------
__global__ void aggregate40_final_kernel(const float* __restrict__ b0,
                                         const float* __restrict__ b1,
                                         float* __restrict__ out, int n) {
    int tid = threadIdx.x;
    int node = blockIdx.x * 32 + tid / 10;
    int c4 = tid % 10;
    if (node >= n) return;
    int beg = g_rowptr[node], end = g_rowptr[node + 1];
    float4 acc = make_float4(0.f, 0.f, 0.f, 0.f);
    int e = beg;
    for (; e + 4 <= end; e += 4) {
        int c0 = g_col[e], c1 = g_col[e + 1], c2 = g_col[e + 2], c3 = g_col[e + 3];
        uint2 p0 = *(const uint2*)&g_t[(size_t)c0 * NCLS + c4 * 4];
        uint2 p1 = *(const uint2*)&g_t[(size_t)c1 * NCLS + c4 * 4];
        uint2 p2 = *(const uint2*)&g_t[(size_t)c2 * NCLS + c4 * 4];
        uint2 p3 = *(const uint2*)&g_t[(size_t)c3 * NCLS + c4 * 4];
        float2 a0 = __half22float2(*(const __half2*)&p0.x);
        float2 b0v = __half22float2(*(const __half2*)&p0.y);
        float2 a1 = __half22float2(*(const __half2*)&p1.x);
        float2 b1v = __half22float2(*(const __half2*)&p1.y);
        float2 a2 = __half22float2(*(const __half2*)&p2.x);
        float2 b2v = __half22float2(*(const __half2*)&p2.y);
        float2 a3 = __half22float2(*(const __half2*)&p3.x);
        float2 b3v = __half22float2(*(const __half2*)&p3.y);
        acc.x += (a0.x + a1.x) + (a2.x + a3.x);
        acc.y += (a0.y + a1.y) + (a2.y + a3.y);
        acc.z += (b0v.x + b1v.x) + (b2v.x + b3v.x);
        acc.w += (b0v.y + b1v.y) + (b2v.y + b3v.y);
    }
    for (; e < end; e++) {
        uint2 p = *(const uint2*)&g_t[(size_t)g_col[e] * NCLS + c4 * 4];
        float2 a = __half22float2(*(const __half2*)&p.x);
        float2 b = __half22float2(*(const __half2*)&p.y);
        acc.x += a.x; acc.y += a.y; acc.z += b.x; acc.w += b.y;
    }
    float s = g_invdeg[node];
    float4 u  = *(const float4*)&g_u[(size_t)node * NCLS + c4 * 4];
    float4 v0 = *(const float4*)&b0[c4 * 4];
    float4 v1 = *(const float4*)&b1[c4 * 4];
    *(float4*)&out[(size_t)node * NCLS + c4 * 4] =
        make_float4(acc.x * s + u.x + v0.x + v1.x,
                    acc.y * s + u.y + v0.y + v1.y,
                    acc.z * s + u.z + v0.z + v1.z,
                    acc.w * s + u.w + v0.w + v1.w);
}

// ---------------- launch --------------------------------------------------
extern "C" void kernel_launch(void* const* d_in, const int* in_sizes, int n_in,
                              void* d_out, int out_size) {
    const float* x     = (const float*)d_in[0];
    const void*  edges = (const void*)d_in[1];
    const float* w1_l = (const float*)d_in[2];
    const float* b1_l = (const float*)d_in[3];
    const float* w1_r = (const float*)d_in[4];
    const float* b1_r = (const float*)d_in[5];
    const float* w2_l = (const float*)d_in[6];
    const float* b2_l = (const float*)d_in[7];
    const float* w2_r = (const float*)d_in[8];
    const float* b2_r = (const float*)d_in[9];
    float* out = (float*)d_out;

    int N = in_sizes[0] / F;
    int E = in_sizes[1] / 2;
    int nb = (N + SCAN_TILE - 1) / SCAN_TILE;
    int e4blocks = (E / 4 + 255) / 256 + 1;   // 4 edges per thread

    // one-time resources (created on the uncaptured correctness call)
    static cudaStream_t s2 = nullptr;
    static cudaEvent_t evFork = nullptr, evJoin = nullptr;
    static int once = 0;
    if (!once) {
        cudaStreamCreateWithFlags(&s2, cudaStreamNonBlocking);
        cudaEventCreateWithFlags(&evFork, cudaEventDisableTiming);
        cudaEventCreateWithFlags(&evJoin, cudaEventDisableTiming);
        cudaFuncSetAttribute(gemm1_tc_kernel,
                             cudaFuncAttributeMaxDynamicSharedMemorySize,
                             2 * STAGE_B);
        once = 1;
    }

    // fork: converts on s2, CSR chain on main stream
    cudaEventRecord(evFork, 0);
    cudaStreamWaitEvent(s2, evFork, 0);
    convert_weights_kernel<<<(W1_Q + W2_Q + 255) / 256, 256, 0, s2>>>(w1_l, w1_r,
                                                                     w2_l, w2_r);
    convert_x_kernel<<<(N * (F / 4) + 255) / 256, 256, 0, s2>>>(x, N);
    cudaEventRecord(evJoin, s2);

    init_kernel<<<(N + 255) / 256, 256>>>((const int*)edges, N);
    degree_kernel<<<e4blocks, 256>>>(edges, E);
    scan_lookback_kernel<<<nb, SCAN_TILE>>>(N, E);
    scatter_kernel<<<e4blocks, 256>>>(edges, E);

    // join before aggregate (needs g_Ah x-part) and gemm1 (needs weights)
    cudaStreamWaitEvent(0, evJoin, 0);

    // Layer 1: agg(fp16) -> fp16 tensor-core GEMM + bias + relu (h fp16)
    dim3 aggBlock(32, 8);
    aggregate_kernel<<<(N + 7) / 8, aggBlock>>>(N);
    {
        dim3 grid((N + 127) / 128, F / 128);
        gemm1_tc_kernel<<<grid, 256, 2 * STAGE_B>>>(b1_l, b1_r, N);
    }

    // Layer 2: fp16 TC dual projection, fused aggregate+final
    gemm40_tc_kernel<<<(N + 127) / 128, 256>>>(N);
    aggregate40_final_kernel<<<(N + 31) / 32, 320>>>(b2_l, b2_r, out, N);
}

// round 17
// speedup vs baseline: 1.0095x; 1.0095x over previous
#include <cuda_runtime.h>
#include <cuda_fp16.h>
#include <cstdint>

// Problem constants (fixed by reference_code)
#define NMAX 50000
#define EMAX 800000
#define F    256
#define AK   512          // concat K for layer-1 GEMM (agg | x)
#define NCLS 40
#define N2   80           // combined layer-2 output width [w2_l | w2_r]
#define SCAN_TILE 1024
#define NBLK_MAX  64

// ---------------- scratch (static device globals; no runtime allocation) ----
__device__ int   g_is64;
__device__ int   g_deg[NMAX];
__device__ int   g_rowptr[NMAX + 1];
__device__ int   g_col[EMAX];
__device__ int   g_pos[EMAX];            // per-edge slot within dst bucket
__device__ unsigned long long g_scan_state[NBLK_MAX];  // (flag<<62)|value
__device__ int   g_scan_ticket;
__device__ float g_invdeg[NMAX];
__device__ __align__(16) __half g_Ah[(size_t)NMAX * AK];   // [agg | x] fp16
__device__ __align__(16) __half g_Bh[(size_t)F * AK];      // [w1_l | w1_r] fp16
__device__ __align__(16) __half g_Hh[(size_t)NMAX * F];    // relu(h) fp16
__device__ __align__(16) __half g_B2h[(size_t)N2 * F];     // [w2_l | w2_r] fp16
__device__ __align__(16) __half g_t[(size_t)NMAX * NCLS];  // h @ w2_l^T (fp16)
__device__ __align__(16) float g_u[(size_t)NMAX * NCLS];   // h @ w2_r^T (fp32)

// ---------------- PTX helpers ----------------------------------------------
__device__ __forceinline__ void ldsm_x4(uint32_t& r0, uint32_t& r1,
                                        uint32_t& r2, uint32_t& r3, uint32_t addr) {
    asm volatile("ldmatrix.sync.aligned.m8n8.x4.shared.b16 {%0,%1,%2,%3},[%4];"
                 : "=r"(r0), "=r"(r1), "=r"(r2), "=r"(r3) : "r"(addr));
}
__device__ __forceinline__ void ldsm_x2(uint32_t& r0, uint32_t& r1, uint32_t addr) {
    asm volatile("ldmatrix.sync.aligned.m8n8.x2.shared.b16 {%0,%1},[%2];"
                 : "=r"(r0), "=r"(r1) : "r"(addr));
}
__device__ __forceinline__ void mma_f16(float* c, const uint32_t* a, const uint32_t* b) {
    asm volatile("mma.sync.aligned.m16n8k16.row.col.f32.f16.f16.f32 "
                 "{%0,%1,%2,%3},{%4,%5,%6,%7},{%8,%9},{%0,%1,%2,%3};"
                 : "+f"(c[0]), "+f"(c[1]), "+f"(c[2]), "+f"(c[3])
                 : "r"(a[0]), "r"(a[1]), "r"(a[2]), "r"(a[3]), "r"(b[0]), "r"(b[1]));
}
__device__ __forceinline__ void cp16(uint32_t saddr, const void* gaddr, int sz) {
    asm volatile("cp.async.cg.shared.global [%0],[%1],16,%2;"
                 :: "r"(saddr), "l"(gaddr), "r"(sz));
}
__device__ __forceinline__ void cp_commit() {
    asm volatile("cp.async.commit_group;");
}
template <int N>
__device__ __forceinline__ void cp_wait() {
    asm volatile("cp.async.wait_group %0;" :: "n"(N));
}
__device__ __forceinline__ void cp_wait_all() {
    asm volatile("cp.async.commit_group;");
    asm volatile("cp.async.wait_group 0;");
}

__device__ __forceinline__ int edge_at(const void* edges, size_t idx) {
    if (g_is64) return (int)((const long long*)edges)[idx];
    return ((const int*)edges)[idx];
}

// ---------------- init: scan state + dtype probe (deg zeroed via memset) ----
__global__ void init_kernel(const int* __restrict__ v) {
    if (threadIdx.x < NBLK_MAX) g_scan_state[threadIdx.x] = 0ULL;
    __shared__ int any_nonzero;
    if (threadIdx.x == 0) { any_nonzero = 0; g_scan_ticket = 0; }
    __syncthreads();
    if (v[2 * threadIdx.x + 1] != 0) atomicOr(&any_nonzero, 1);
    __syncthreads();
    if (threadIdx.x == 0) g_is64 = (any_nonzero == 0) ? 1 : 0;
}

// ---------------- CSR build ------------------------------------------------
// degree pass (1 edge/thread, max TLP): records per-edge slot in g_pos
__global__ void degree_kernel(const void* __restrict__ edges, int E) {
    int e = blockIdx.x * blockDim.x + threadIdx.x;
    if (e < E) {
        int d = edge_at(edges, (size_t)E + e);
        g_pos[e] = atomicAdd(&g_deg[d], 1);
    }
}
__device__ __forceinline__ int block_incl_scan(int d, int* total) {
    __shared__ int wsum[32];
    int lane = threadIdx.x & 31, wid = threadIdx.x >> 5;
    int v = d;
#pragma unroll
    for (int o = 1; o < 32; o <<= 1) {
        int t = __shfl_up_sync(0xffffffffu, v, o);
        if (lane >= o) v += t;
    }
    if (lane == 31) wsum[wid] = v;
    __syncthreads();
    if (wid == 0) {
        int w = wsum[lane];
#pragma unroll
        for (int o = 1; o < 32; o <<= 1) {
            int t = __shfl_up_sync(0xffffffffu, w, o);
            if (lane >= o) w += t;
        }
        wsum[lane] = w;
    }
    __syncthreads();
    int incl = v + (wid > 0 ? wsum[wid - 1] : 0);
    *total = wsum[31];
    __syncthreads();
    return incl;
}

// single-pass decoupled-lookback scan: g_deg -> g_rowptr (+invdeg, rowptr[n])
__global__ void scan_lookback_kernel(int n, int E) {
    __shared__ int s_bid;
    __shared__ int s_prefix;
    if (threadIdx.x == 0) s_bid = atomicAdd(&g_scan_ticket, 1);
    __syncthreads();
    int bid = s_bid;
    int i = bid * SCAN_TILE + threadIdx.x;
    int d = (i < n) ? g_deg[i] : 0;
    int total;
    int incl = block_incl_scan(d, &total);
    if (threadIdx.x == 0) {
        if (bid == 0) {
            atomicExch(&g_scan_state[0], (2ULL << 62) | (unsigned)total);
            s_prefix = 0;
        } else {
            atomicExch(&g_scan_state[bid], (1ULL << 62) | (unsigned)total);
            int prefix = 0;
            int j = bid - 1;
            while (j >= 0) {
                unsigned long long st = atomicAdd(&g_scan_state[j], 0ULL);
                unsigned long long flag = st >> 62;
                if (flag == 2) { prefix += (int)(st & 0xFFFFFFFFu); break; }
                if (flag == 1) { prefix += (int)(st & 0xFFFFFFFFu); j--; }
            }
            atomicExch(&g_scan_state[bid], (2ULL << 62) | (unsigned)(prefix + total));
            s_prefix = prefix;
        }
    }
    __syncthreads();
    if (i < n) {
        g_rowptr[i] = s_prefix + incl - d;
        g_invdeg[i] = 1.0f / (float)(d > 0 ? d : 1);
        if (i == n - 1) g_rowptr[n] = E;
    }
}

// scatter without atomics (1 edge/thread): slot precomputed in degree pass
__global__ void scatter_kernel(const void* __restrict__ edges, int E) {
    int e = blockIdx.x * blockDim.x + threadIdx.x;
    if (e < E) {
        int srcv = edge_at(edges, e);
        int d    = edge_at(edges, (size_t)E + e);
        g_col[g_rowptr[d] + g_pos[e]] = srcv;
    }
}

// ---------------- merged weight conversions (fp16) ---------------------------
#define W1_Q (F * (F / 4))          // 16384 float4s
#define W2_Q (N2 * (F / 4))         // 5120 float4s
__device__ __forceinline__ uint2 to_h4(float4 v) {
    __half2 h0 = __floats2half2_rn(v.x, v.y);
    __half2 h1 = __floats2half2_rn(v.z, v.w);
    return make_uint2(*(const uint32_t*)&h0, *(const uint32_t*)&h1);
}
__global__ void convert_weights_kernel(const float* __restrict__ w1_l,
                                       const float* __restrict__ w1_r,
                                       const float* __restrict__ w2_l,
                                       const float* __restrict__ w2_r) {
    int idx = blockIdx.x * blockDim.x + threadIdx.x;
    if (idx < W1_Q) {
        int row = idx / (F / 4), c4 = idx % (F / 4);
        float4 vl = *(const float4*)&w1_l[(size_t)row * F + c4 * 4];
        float4 vr = *(const float4*)&w1_r[(size_t)row * F + c4 * 4];
        size_t o = (size_t)row * AK + c4 * 4;
        *(uint2*)&g_Bh[o]     = to_h4(vl);
        *(uint2*)&g_Bh[o + F] = to_h4(vr);
    } else if (idx < W1_Q + W2_Q) {
        int j = idx - W1_Q;
        int row = j / (F / 4), c4 = j % (F / 4);
        const float* src = (row < NCLS) ? &w2_l[(size_t)row * F + c4 * 4]
                                        : &w2_r[(size_t)(row - NCLS) * F + c4 * 4];
        *(uint2*)&g_B2h[(size_t)row * F + c4 * 4] = to_h4(*(const float4*)src);
    }
}

// ---------------- x conversion: fp16 into A cols [256,512) ------------------
__global__ void convert_x_kernel(const float* __restrict__ x, int n) {
    int idx = blockIdx.x * blockDim.x + threadIdx.x;
    if (idx >= n * (F / 4)) return;
    int row = idx / (F / 4), c4 = idx % (F / 4);
    float4 v = *(const float4*)&x[(size_t)row * F + c4 * 4];
    *(uint2*)&g_Ah[(size_t)row * AK + F + c4 * 4] = to_h4(v);
}

// ---------------- mean aggregation (256-dim) from fp16 x-part ---------------
__global__ void aggregate_kernel(int n) {
    int node = blockIdx.x * blockDim.y + threadIdx.y;
    if (node >= n) return;
    int lane = threadIdx.x;
    int beg = g_rowptr[node], end = g_rowptr[node + 1];
    const uint4* xh = (const uint4*)g_Ah;   // row stride = 64 uint4; x-part +32
    float acc[8];
#pragma unroll
    for (int i = 0; i < 8; i++) acc[i] = 0.f;
    int e = beg;
    for (; e + 2 <= end; e += 2) {
        uint4 p0 = xh[(size_t)g_col[e] * 64 + 32 + lane];
        uint4 p1 = xh[(size_t)g_col[e + 1] * 64 + 32 + lane];
        const __half2* q0 = (const __half2*)&p0;
        const __half2* q1 = (const __half2*)&p1;
#pragma unroll
        for (int j = 0; j < 4; j++) {
            float2 f0 = __half22float2(q0[j]);
            float2 f1 = __half22float2(q1[j]);
            acc[j * 2]     += f0.x + f1.x;
            acc[j * 2 + 1] += f0.y + f1.y;
        }
    }
    if (e < end) {
        uint4 p0 = xh[(size_t)g_col[e] * 64 + 32 + lane];
        const __half2* q0 = (const __half2*)&p0;
#pragma unroll
        for (int j = 0; j < 4; j++) {
            float2 f0 = __half22float2(q0[j]);
            acc[j * 2]     += f0.x;
            acc[j * 2 + 1] += f0.y;
        }
    }
    float s = g_invdeg[node];
    uint4 o;
    __half2 h0 = __floats2half2_rn(acc[0] * s, acc[1] * s);
    __half2 h1 = __floats2half2_rn(acc[2] * s, acc[3] * s);
    __half2 h2 = __floats2half2_rn(acc[4] * s, acc[5] * s);
    __half2 h3 = __floats2half2_rn(acc[6] * s, acc[7] * s);
    o.x = *(const uint32_t*)&h0; o.y = *(const uint32_t*)&h1;
    o.z = *(const uint32_t*)&h2; o.w = *(const uint32_t*)&h3;
    *(uint4*)&g_Ah[(size_t)node * AK + lane * 8] = o;
}

// ---------------- GEMM1 (fp16 tensor cores, single pass, 2-stage pipeline) --
#define TSTRIDE 40      // halfs per smem row (80B) -> conflict-free ldsm
#define TILE_B  (128 * TSTRIDE * 2)   // bytes per tile = 10240
#define STAGE_B (2 * TILE_B)          // A + B tiles = 20480
extern __shared__ __align__(16) __half g1_smem[];
__global__ __launch_bounds__(256) void gemm1_tc_kernel(const float* __restrict__ bias0,
                                                       const float* __restrict__ bias1,
                                                       int M) {
    const uint32_t sb0 = (uint32_t)__cvta_generic_to_shared(g1_smem);
    int bm = blockIdx.x * 128, bn = blockIdx.y * 128;
    int tid = threadIdx.x, wid = tid >> 5, lane = tid & 31;
    int wm = (wid >> 2) * 64, wn = (wid & 3) * 32;

    float acc[4][4][4];
#pragma unroll
    for (int mf = 0; mf < 4; mf++)
#pragma unroll
        for (int nf = 0; nf < 4; nf++)
#pragma unroll
            for (int r = 0; r < 4; r++) acc[mf][nf][r] = 0.f;

    auto load_chunk = [&](int kc, int stage) {
        int k0 = kc * 32;
        uint32_t sbase = sb0 + stage * STAGE_B;
#pragma unroll
        for (int i = 0; i < 4; i++) {
            int idx = tid + i * 256;
            int t   = idx >> 9;          // 0 = A, 1 = B
            int rem = idx & 511;
            int row = rem >> 2, ch = rem & 3;
            uint32_t sa = sbase + t * TILE_B + row * 80 + ch * 16;
            if (t == 0) {
                int grow = bm + row;
                int gr = grow < M ? grow : (M - 1);
                cp16(sa, g_Ah + (size_t)gr * AK + k0 + ch * 8, grow < M ? 16 : 0);
            } else {
                cp16(sa, g_Bh + (size_t)(bn + row) * AK + k0 + ch * 8, 16);
            }
        }
        cp_commit();
    };

    load_chunk(0, 0);
#pragma unroll 1
    for (int kc = 0; kc < 16; kc++) {
        int stage = kc & 1;
        if (kc + 1 < 16) {
            load_chunk(kc + 1, stage ^ 1);
            cp_wait<1>();
        } else {
            cp_wait<0>();
        }
        __syncthreads();
        uint32_t sb = sb0 + stage * STAGE_B;
#pragma unroll
        for (int ks = 0; ks < 32; ks += 16) {
            uint32_t a[4][4], b[4][2];
            int akb = (ks + ((lane >> 4) << 3)) * 2;
#pragma unroll
            for (int mf = 0; mf < 4; mf++) {
                int row = wm + mf * 16 + (lane & 15);
                ldsm_x4(a[mf][0], a[mf][1], a[mf][2], a[mf][3],
                        sb + row * 80 + akb);
            }
            int brow0 = wn + ((lane >> 4) << 3) + (lane & 7);
            int bkb = (ks + (((lane >> 3) & 1) << 3)) * 2;
#pragma unroll
            for (int nf2 = 0; nf2 < 2; nf2++) {
                int row = brow0 + nf2 * 16;
                uint32_t r0, r1, r2, r3;
                ldsm_x4(r0, r1, r2, r3, sb + TILE_B + row * 80 + bkb);
                b[nf2 * 2][0] = r0; b[nf2 * 2][1] = r1;
                b[nf2 * 2 + 1][0] = r2; b[nf2 * 2 + 1][1] = r3;
            }
#pragma unroll
            for (int mf = 0; mf < 4; mf++)
#pragma unroll
                for (int nf = 0; nf < 4; nf++)
                    mma_f16(acc[mf][nf], a[mf], b[nf]);
        }
        __syncthreads();
    }
#pragma unroll
    for (int nf = 0; nf < 4; nf++) {
        int c = bn + wn + nf * 8 + 2 * (lane & 3);
        float bb0 = bias0[c] + bias1[c];
        float bb1 = bias0[c + 1] + bias1[c + 1];
#pragma unroll
        for (int mf = 0; mf < 4; mf++) {
            int r0 = bm + wm + mf * 16 + (lane >> 2);
            int r1 = r0 + 8;
            if (r0 < M) {
                *(__half2*)&g_Hh[(size_t)r0 * F + c] =
                    __floats2half2_rn(fmaxf(acc[mf][nf][0] + bb0, 0.f),
                                      fmaxf(acc[mf][nf][1] + bb1, 0.f));
            }
            if (r1 < M) {
                *(__half2*)&g_Hh[(size_t)r1 * F + c] =
                    __floats2half2_rn(fmaxf(acc[mf][nf][2] + bb0, 0.f),
                                      fmaxf(acc[mf][nf][3] + bb1, 0.f));
            }
        }
    }
}

// ---------------- GEMM40 (fp16 TC): g_t (fp16) | g_u (fp32) = h @ B2^T ------
#define A2_B (128 * 80)
#define B2_B (80 * 80)
__global__ __launch_bounds__(256) void gemm40_tc_kernel(int M) {
    __shared__ __align__(16) __half smem[(A2_B + B2_B) / 2];
    const uint32_t sb = (uint32_t)__cvta_generic_to_shared(smem);
    int bm = blockIdx.x * 128;
    int tid = threadIdx.x, wid = tid >> 5, lane = tid & 31;
    int wm = (wid & 3) * 32, wn = (wid >> 2) * 40;

    float acc[2][5][4];
#pragma unroll
    for (int mf = 0; mf < 2; mf++)
#pragma unroll
        for (int nf = 0; nf < 5; nf++)
#pragma unroll
            for (int r = 0; r < 4; r++) acc[mf][nf][r] = 0.f;

#pragma unroll 1
    for (int kc = 0; kc < 8; kc++) {
        int k0 = kc * 32;
        for (int idx = tid; idx < 832; idx += 256) {
            if (idx < 512) {
                int row = idx >> 2, ch = idx & 3;
                int grow = bm + row;
                int gr = grow < M ? grow : (M - 1);
                cp16(sb + row * 80 + ch * 16,
                     g_Hh + (size_t)gr * F + k0 + ch * 8, grow < M ? 16 : 0);
            } else {
                int j = idx - 512;
                int row = j >> 2, ch = j & 3;
                cp16(sb + A2_B + row * 80 + ch * 16,
                     g_B2h + (size_t)row * F + k0 + ch * 8, 16);
            }
        }
        cp_wait_all();
        __syncthreads();
#pragma unroll
        for (int ks = 0; ks < 32; ks += 16) {
            uint32_t a[2][4], b[5][2];
            int akb = (ks + ((lane >> 4) << 3)) * 2;
#pragma unroll
            for (int mf = 0; mf < 2; mf++) {
                int row = wm + mf * 16 + (lane & 15);
                ldsm_x4(a[mf][0], a[mf][1], a[mf][2], a[mf][3],
                        sb + row * 80 + akb);
            }
            int bkb = (ks + (((lane >> 3) & 1) << 3)) * 2;
            int brow0 = wn + ((lane >> 4) << 3) + (lane & 7);
#pragma unroll
            for (int nf2 = 0; nf2 < 2; nf2++) {
                int row = brow0 + nf2 * 16;
                uint32_t r0, r1, r2, r3;
                ldsm_x4(r0, r1, r2, r3, sb + A2_B + row * 80 + bkb);
                b[nf2 * 2][0] = r0; b[nf2 * 2][1] = r1;
                b[nf2 * 2 + 1][0] = r2; b[nf2 * 2 + 1][1] = r3;
            }
            {
                int row = wn + 32 + (lane & 7);
                ldsm_x2(b[4][0], b[4][1], sb + A2_B + row * 80 + bkb);
            }
#pragma unroll
            for (int mf = 0; mf < 2; mf++)
#pragma unroll
                for (int nf = 0; nf < 5; nf++)
                    mma_f16(acc[mf][nf], a[mf], b[nf]);
        }
        __syncthreads();
    }
    bool is_u = (wid >> 2) != 0;
#pragma unroll
    for (int nf = 0; nf < 5; nf++) {
        int c = (wn % 40) + nf * 8 + 2 * (lane & 3);
#pragma unroll
        for (int mf = 0; mf < 2; mf++) {
            int r0 = bm + wm + mf * 16 + (lane >> 2);
            int r1 = r0 + 8;
            if (is_u) {
                if (r0 < M) {
                    g_u[(size_t)r0 * NCLS + c]     = acc[mf][nf][0];
                    g_u[(size_t)r0 * NCLS + c + 1] = acc[mf][nf][1];
                }
                if (r1 < M) {
                    g_u[(size_t)r1 * NCLS + c]     = acc[mf][nf][2];
                    g_u[(size_t)r1 * NCLS + c + 1] = acc[mf][nf][3];
                }
            } else {
                if (r0 < M)
                    *(__half2*)&g_t[(size_t)r0 * NCLS + c] =
                        __floats2half2_rn(acc[mf][nf][0], acc[mf][nf][1]);
                if (r1 < M)
                    *(__half2*)&g_t[(size_t)r1 * NCLS + c] =
                        __floats2half2_rn(acc[mf][nf][2], acc[mf][nf][3]);
            }
        }
    }
}

// ---------------- mean aggregation (40-dim, fp16 t) + fused final -----------
__global__ void aggregate40_final_kernel(const float* __restrict__ b0,
                                         const float* __restrict__ b1,
                                         float* __restrict__ out, int n) {
    int tid = threadIdx.x;
    int node = blockIdx.x * 32 + tid / 10;
    int c4 = tid % 10;
    if (node >= n) return;
    int beg = g_rowptr[node], end = g_rowptr[node + 1];
    float4 acc = make_float4(0.f, 0.f, 0.f, 0.f);
    int e = beg;
    for (; e + 4 <= end; e += 4) {
        int c0 = g_col[e], c1 = g_col[e + 1], c2 = g_col[e + 2], c3 = g_col[e + 3];
        uint2 p0 = *(const uint2*)&g_t[(size_t)c0 * NCLS + c4 * 4];
        uint2 p1 = *(const uint2*)&g_t[(size_t)c1 * NCLS + c4 * 4];
        uint2 p2 = *(const uint2*)&g_t[(size_t)c2 * NCLS + c4 * 4];
        uint2 p3 = *(const uint2*)&g_t[(size_t)c3 * NCLS + c4 * 4];
        float2 a0 = __half22float2(*(const __half2*)&p0.x);
        float2 b0v = __half22float2(*(const __half2*)&p0.y);
        float2 a1 = __half22float2(*(const __half2*)&p1.x);
        float2 b1v = __half22float2(*(const __half2*)&p1.y);
        float2 a2 = __half22float2(*(const __half2*)&p2.x);
        float2 b2v = __half22float2(*(const __half2*)&p2.y);
        float2 a3 = __half22float2(*(const __half2*)&p3.x);
        float2 b3v = __half22float2(*(const __half2*)&p3.y);
        acc.x += (a0.x + a1.x) + (a2.x + a3.x);
        acc.y += (a0.y + a1.y) + (a2.y + a3.y);
        acc.z += (b0v.x + b1v.x) + (b2v.x + b3v.x);
        acc.w += (b0v.y + b1v.y) + (b2v.y + b3v.y);
    }
    for (; e < end; e++) {
        uint2 p = *(const uint2*)&g_t[(size_t)g_col[e] * NCLS + c4 * 4];
        float2 a = __half22float2(*(const __half2*)&p.x);
        float2 b = __half22float2(*(const __half2*)&p.y);
        acc.x += a.x; acc.y += a.y; acc.z += b.x; acc.w += b.y;
    }
    float s = g_invdeg[node];
    float4 u  = *(const float4*)&g_u[(size_t)node * NCLS + c4 * 4];
    float4 v0 = *(const float4*)&b0[c4 * 4];
    float4 v1 = *(const float4*)&b1[c4 * 4];
    *(float4*)&out[(size_t)node * NCLS + c4 * 4] =
        make_float4(acc.x * s + u.x + v0.x + v1.x,
                    acc.y * s + u.y + v0.y + v1.y,
                    acc.z * s + u.z + v0.z + v1.z,
                    acc.w * s + u.w + v0.w + v1.w);
}

// ---------------- launch --------------------------------------------------
extern "C" void kernel_launch(void* const* d_in, const int* in_sizes, int n_in,
                              void* d_out, int out_size) {
    const float* x     = (const float*)d_in[0];
    const void*  edges = (const void*)d_in[1];
    const float* w1_l = (const float*)d_in[2];
    const float* b1_l = (const float*)d_in[3];
    const float* w1_r = (const float*)d_in[4];
    const float* b1_r = (const float*)d_in[5];
    const float* w2_l = (const float*)d_in[6];
    const float* b2_l = (const float*)d_in[7];
    const float* w2_r = (const float*)d_in[8];
    const float* b2_r = (const float*)d_in[9];
    float* out = (float*)d_out;

    int N = in_sizes[0] / F;
    int E = in_sizes[1] / 2;
    int nb = (N + SCAN_TILE - 1) / SCAN_TILE;

    // one-time resources (created on the uncaptured correctness call)
    static cudaStream_t s2 = nullptr;
    static cudaEvent_t evFork = nullptr, evJoin = nullptr;
    static void* degPtr = nullptr;
    static int once = 0;
    if (!once) {
        cudaStreamCreateWithFlags(&s2, cudaStreamNonBlocking);
        cudaEventCreateWithFlags(&evFork, cudaEventDisableTiming);
        cudaEventCreateWithFlags(&evJoin, cudaEventDisableTiming);
        cudaGetSymbolAddress(&degPtr, g_deg);
        cudaFuncSetAttribute(gemm1_tc_kernel,
                             cudaFuncAttributeMaxDynamicSharedMemorySize,
                             2 * STAGE_B);
        once = 1;
    }

    // fork: converts on s2, CSR chain on main stream
    cudaEventRecord(evFork, 0);
    cudaStreamWaitEvent(s2, evFork, 0);
    convert_weights_kernel<<<(W1_Q + W2_Q + 255) / 256, 256, 0, s2>>>(w1_l, w1_r,
                                                                     w2_l, w2_r);
    convert_x_kernel<<<(N * (F / 4) + 255) / 256, 256, 0, s2>>>(x, N);
    cudaEventRecord(evJoin, s2);

    cudaMemsetAsync(degPtr, 0, (size_t)N * sizeof(int), 0);
    init_kernel<<<1, 256>>>((const int*)edges);
    degree_kernel<<<(E + 255) / 256, 256>>>(edges, E);
    scan_lookback_kernel<<<nb, SCAN_TILE>>>(N, E);
    scatter_kernel<<<(E + 255) / 256, 256>>>(edges, E);

    // join before aggregate (needs g_Ah x-part) and gemm1 (needs weights)
    cudaStreamWaitEvent(0, evJoin, 0);

    // Layer 1: agg(fp16) -> fp16 tensor-core GEMM + bias + relu (h fp16)
    dim3 aggBlock(32, 8);
    aggregate_kernel<<<(N + 7) / 8, aggBlock>>>(N);
    {
        dim3 grid((N + 127) / 128, F / 128);
        gemm1_tc_kernel<<<grid, 256, 2 * STAGE_B>>>(b1_l, b1_r, N);
    }

    // Layer 2: fp16 TC dual projection, fused aggregate+final
    gemm40_tc_kernel<<<(N + 127) / 128, 256>>>(N);
    aggregate40_final_kernel<<<(N + 31) / 32, 320>>>(b2_l, b2_r, out, N);
}